// round 15
// baseline (speedup 1.0000x reference)
#include <cuda_runtime.h>
#include <cuda_fp16.h>
#include <cstdint>

#define T_DIM 2048
#define B_DIM 2
#define E_DIM 1024
#define H_DIM 16
#define D_DIM 64
#define M_DIM (T_DIM * B_DIM)

__device__ __half g_q[B_DIM * H_DIM * T_DIM * D_DIM];
__device__ __half g_k[B_DIM * H_DIM * T_DIM * D_DIM];
__device__ __half g_v[B_DIM * H_DIM * T_DIM * D_DIM];
__device__ __half g_attn[T_DIM * B_DIM * E_DIM];
__device__ float  g_bias[B_DIM * T_DIM];
__device__ __half g_in_h[3 * M_DIM * E_DIM];
__device__ __half g_w_h[4 * E_DIM * E_DIM];

__device__ __forceinline__ void cp16h(__half* smem, const __half* gmem) {
    unsigned s = (unsigned)__cvta_generic_to_shared(smem);
    asm volatile("cp.async.cg.shared.global [%0], [%1], 16;\n" :: "r"(s), "l"(gmem));
}
__device__ __forceinline__ void cp_commit() { asm volatile("cp.async.commit_group;\n"); }
template <int N> __device__ __forceinline__ void cp_wait() {
    asm volatile("cp.async.wait_group %0;\n" :: "n"(N));
}

__device__ __forceinline__ void mma16(float* d, const unsigned* a, unsigned b0, unsigned b1) {
    asm volatile(
        "mma.sync.aligned.m16n8k16.row.col.f32.f16.f16.f32 "
        "{%0,%1,%2,%3},{%4,%5,%6,%7},{%8,%9},{%0,%1,%2,%3};"
        : "+f"(d[0]), "+f"(d[1]), "+f"(d[2]), "+f"(d[3])
        : "r"(a[0]), "r"(a[1]), "r"(a[2]), "r"(a[3]), "r"(b0), "r"(b1));
}

__device__ __forceinline__ void ldsm4(unsigned* r, unsigned addr) {
    asm volatile("ldmatrix.sync.aligned.m8n8.x4.shared.b16 {%0,%1,%2,%3}, [%4];"
                 : "=r"(r[0]), "=r"(r[1]), "=r"(r[2]), "=r"(r[3]) : "r"(addr));
}
__device__ __forceinline__ void ldsm4t(unsigned* r, unsigned addr) {
    asm volatile("ldmatrix.sync.aligned.m8n8.x4.trans.shared.b16 {%0,%1,%2,%3}, [%4];"
                 : "=r"(r[0]), "=r"(r[1]), "=r"(r[2]), "=r"(r[3]) : "r"(addr));
}

// ---------------------------------------------------------------------------
__global__ void tohalf_kernel(const float4* __restrict__ q, const float4* __restrict__ k,
                              const float4* __restrict__ v, const float4* __restrict__ wq,
                              const float4* __restrict__ wk, const float4* __restrict__ wv,
                              const float4* __restrict__ wo, __half* __restrict__ din,
                              __half* __restrict__ dw)
{
    const int IN4 = M_DIM * E_DIM / 4;
    const int W4  = E_DIM * E_DIM / 4;
    int i = blockIdx.x * blockDim.x + threadIdx.x;
    const float4* s;
    __half* d;
    if (i < 3 * IN4) {
        s = (i < IN4) ? q + i : (i < 2 * IN4 ? k + (i - IN4) : v + (i - 2 * IN4));
        d = din + (size_t)i * 4;
    } else {
        int j = i - 3 * IN4;
        s = (j < W4) ? wq + j : j < 2 * W4 ? wk + (j - W4) : j < 3 * W4 ? wv + (j - 2 * W4)
                                                                        : wo + (j - 3 * W4);
        d = dw + (size_t)j * 4;
    }
    float4 x = *s;
    __half2 h01 = __floats2half2_rn(x.x, x.y);
    __half2 h23 = __floats2half2_rn(x.z, x.w);
    uint2 u;
    u.x = *(unsigned*)&h01;
    u.y = *(unsigned*)&h23;
    *(uint2*)d = u;
}

__global__ void mask_bias_kernel(const unsigned char* __restrict__ mask, float* __restrict__ bias) {
    int i = blockIdx.x * blockDim.x + threadIdx.x;
    if (i < B_DIM * T_DIM) bias[i] = mask[i] ? -60000.0f : 0.0f;   // fp16-safe -inf proxy
}

// ---------------------------------------------------------------------------
// fp16 GEMM: 128x128 block, 64x64 warp tile, BK=64, 3-stage cp.async
// (1 barrier per 64-K chunk), ldmatrix fragments, m16n8k16, fp32 accum.
// ---------------------------------------------------------------------------
struct GemmArgs {
    const __half* A[3];
    const __half* W[3];
    const float* bias[3];
    void* out[3];
    float scale[3];
};

#define GPADH   72
#define GSTAGEH (128 * GPADH)

template <int MODE>
__global__ __launch_bounds__(128, 2)
void gemm_kernel(GemmArgs args)
{
    extern __shared__ __half smh[];   // 3 stages * 2 * GSTAGEH halfs = 110592 B

    const int z    = (MODE == 0) ? blockIdx.z : 0;
    const __half* A = args.A[z];
    const __half* W = args.W[z];
    const float* bias = args.bias[z];
    const float scale = args.scale[z];

    const int tid  = threadIdx.x;
    const int warp = tid >> 5;
    const int lane = tid & 31;
    const int g    = lane >> 2;
    const int tig  = lane & 3;
    const int wm   = warp >> 1;
    const int wn   = warp & 1;
    const int row0 = blockIdx.y * 128;
    const int col0 = blockIdx.x * 128;

    const unsigned smb = (unsigned)__cvta_generic_to_shared(smh);
    const int arow = (lane & 15);
    const int acol = (lane >> 4) * 8;
    const int brow = (lane & 7) + (lane >> 4) * 8;
    const int bcol = ((lane >> 3) & 1) * 8;

    float acc[4][8][4];
    #pragma unroll
    for (int mi = 0; mi < 4; mi++)
        #pragma unroll
        for (int ni = 0; ni < 8; ni++)
            acc[mi][ni][0] = acc[mi][ni][1] = acc[mi][ni][2] = acc[mi][ni][3] = 0.0f;

    const __half* Agb = &A[(size_t)(row0 + tid) * 1024];
    const __half* Wgb = &W[(size_t)(col0 + tid) * 1024];

    auto stage = [&](int kt, int st) {
        __half* Ad = smh + st * 2 * GSTAGEH + tid * GPADH;
        __half* Bd = Ad + GSTAGEH;
        const int k0 = kt * 64;
        #pragma unroll
        for (int c = 0; c < 64; c += 8) {
            cp16h(Ad + c, Agb + k0 + c);
            cp16h(Bd + c, Wgb + k0 + c);
        }
        cp_commit();
    };

    auto compute = [&](int st) {
        const unsigned asb = smb + st * 2 * GSTAGEH * 2;
        const unsigned bsb = asb + GSTAGEH * 2;
        #pragma unroll
        for (int kc = 0; kc < 4; kc++) {
            unsigned af[4][4];
            unsigned bf[4][4];
            #pragma unroll
            for (int mi = 0; mi < 4; mi++)
                ldsm4(af[mi], asb + ((wm * 64 + mi * 16 + arow) * GPADH + kc * 16 + acol) * 2);
            #pragma unroll
            for (int np = 0; np < 4; np++)
                ldsm4(bf[np], bsb + ((wn * 64 + np * 16 + brow) * GPADH + kc * 16 + bcol) * 2);
            #pragma unroll
            for (int mi = 0; mi < 4; mi++)
                #pragma unroll
                for (int np = 0; np < 4; np++) {
                    mma16(acc[mi][np * 2],     af[mi], bf[np][0], bf[np][1]);
                    mma16(acc[mi][np * 2 + 1], af[mi], bf[np][2], bf[np][3]);
                }
        }
    };

    const int NT = 1024 / 64;   // 16
    stage(0, 0);
    stage(1, 1);
    for (int t = 0; t < NT; t++) {
        if (t + 1 < NT) cp_wait<1>();
        else            cp_wait<0>();
        __syncthreads();
        if (t + 2 < NT) stage(t + 2, (t + 2) % 3);
        compute(t % 3);
    }

    float bvals[8][2];
    #pragma unroll
    for (int ni = 0; ni < 8; ni++) {
        int c = col0 + wn * 64 + ni * 8 + 2 * tig;
        bvals[ni][0] = __ldg(&bias[c]);
        bvals[ni][1] = __ldg(&bias[c + 1]);
    }
    #pragma unroll
    for (int mi = 0; mi < 4; mi++) {
        #pragma unroll
        for (int rr = 0; rr < 2; rr++) {
            int r = row0 + wm * 64 + mi * 16 + g + rr * 8;
            #pragma unroll
            for (int ni = 0; ni < 8; ni++) {
                int o = col0 + wn * 64 + ni * 8 + 2 * tig;
                float v0 = (acc[mi][ni][rr * 2]     + bvals[ni][0]) * scale;
                float v1 = (acc[mi][ni][rr * 2 + 1] + bvals[ni][1]) * scale;
                if (MODE == 0) {
                    __half* out = (__half*)args.out[z];
                    int t = r >> 1, b = r & 1;
                    int h = o >> 6, d = o & 63;
                    *(__half2*)&out[(((size_t)(b * H_DIM + h)) * T_DIM + t) * D_DIM + d] =
                        __floats2half2_rn(v0, v1);
                } else {
                    float* out = (float*)args.out[z];
                    *(float2*)&out[(size_t)r * E_DIM + o] = make_float2(v0, v1);
                }
            }
        }
    }
}

// ---------------------------------------------------------------------------
// Flash attention fp16 v4: 256 threads (8 warps x 32 q), 128-key staged
// tiles x 16 iters (body = 2 x 64-key halves), double-buffered K/V,
// Q frags in regs, ldmatrix K/P/V, no-max softmax with h2exp2 (P in fp16).
// ---------------------------------------------------------------------------
#define KSTR 72
#define VSTR 72
#define PSTR 72

#define ATTN_SMEM_HALFS (2 * 128 * KSTR + 2 * 128 * VSTR + 8 * 32 * PSTR)

__global__ __launch_bounds__(256, 1)
void attn_kernel(const __half* __restrict__ q, const __half* __restrict__ k,
                 const __half* __restrict__ v, const float* __restrict__ biasg,
                 __half* __restrict__ out)
{
    extern __shared__ __half smh[];
    __half* Kst = smh;                          // 2 x 128 x KSTR
    __half* Vst = Kst + 2 * 128 * KSTR;         // 2 x 128 x VSTR
    __half* Ps  = Vst + 2 * 128 * VSTR;         // 8 warps x 32 x PSTR

    const int tid  = threadIdx.x;
    const int warp = tid >> 5;
    const int lane = tid & 31;
    const int g    = lane >> 2;
    const int tig  = lane & 3;
    const int qt0  = blockIdx.x * 256;
    const int bh   = blockIdx.y;
    const int b    = bh >> 4;
    const int h    = bh & 15;

    const __half* qb = q + (size_t)bh * T_DIM * D_DIM;
    const __half* kb = k + (size_t)bh * T_DIM * D_DIM;
    const __half* vb = v + (size_t)bh * T_DIM * D_DIM;
    const float* bg = biasg + (size_t)b * T_DIM;
    __half* Pw = Ps + warp * 32 * PSTR;

    const unsigned ksb = (unsigned)__cvta_generic_to_shared(Kst);
    const unsigned vsb = (unsigned)__cvta_generic_to_shared(Vst);
    const unsigned psb = (unsigned)__cvta_generic_to_shared(Pw);

    const int arow = (lane & 15);
    const int acol = (lane >> 4) * 8;
    const int brow = (lane & 7) + (lane >> 4) * 8;
    const int bcol = ((lane >> 3) & 1) * 8;
    const int vrow = (lane & 7) + ((lane >> 3) & 1) * 8;
    const int vcol = (lane >> 4) * 8;

    // Q A-fragments from gmem (once per block)
    unsigned qa[4][2][4];
    {
        const __half* qw = qb + (size_t)(qt0 + warp * 32) * 64;
        #pragma unroll
        for (int kc = 0; kc < 4; kc++)
            #pragma unroll
            for (int m = 0; m < 2; m++) {
                int r0 = m * 16 + g, r1 = r0 + 8;
                qa[kc][m][0] = *(const unsigned*)&qw[r0 * 64 + kc * 16 + 2 * tig];
                qa[kc][m][1] = *(const unsigned*)&qw[r1 * 64 + kc * 16 + 2 * tig];
                qa[kc][m][2] = *(const unsigned*)&qw[r0 * 64 + kc * 16 + 2 * tig + 8];
                qa[kc][m][3] = *(const unsigned*)&qw[r1 * 64 + kc * 16 + 2 * tig + 8];
            }
    }

    float o[8][2][4];
    #pragma unroll
    for (int dj = 0; dj < 8; dj++)
        #pragma unroll
        for (int m = 0; m < 2; m++)
            o[dj][m][0] = o[dj][m][1] = o[dj][m][2] = o[dj][m][3] = 0.0f;
    float lr[4] = {0.0f, 0.0f, 0.0f, 0.0f};

    auto stageKV = [&](int it, int buf) {
        const int s0 = it * 128;
        __half* Kd = Kst + buf * 128 * KSTR;
        __half* Vd = Vst + buf * 128 * VSTR;
        #pragma unroll
        for (int i = 0; i < 4; i++) {
            int idx = tid + i * 256;          // 0..1023
            int r = idx >> 3, c = (idx & 7) * 8;
            cp16h(&Kd[r * KSTR + c], &kb[(size_t)(s0 + r) * 64 + c]);
            cp16h(&Vd[r * VSTR + c], &vb[(size_t)(s0 + r) * 64 + c]);
        }
        cp_commit();
    };

    stageKV(0, 0);
    for (int it = 0; it < 16; it++) {
        cp_wait<0>();
        __syncthreads();
        if (it + 1 < 16) stageKV(it + 1, (it + 1) & 1);

        const unsigned kb0 = ksb + (it & 1) * 128 * KSTR * 2;
        const unsigned vb0 = vsb + (it & 1) * 128 * VSTR * 2;

        #pragma unroll
        for (int hf = 0; hf < 2; hf++) {
            const unsigned kbuf = kb0 + hf * 64 * KSTR * 2;
            const unsigned vbuf = vb0 + hf * 64 * VSTR * 2;
            const float* bgh = bg + it * 128 + hf * 64;

            // ---- S = Q @ K^T ----
            float s[8][2][4];
            #pragma unroll
            for (int j = 0; j < 8; j++)
                #pragma unroll
                for (int m = 0; m < 2; m++)
                    s[j][m][0] = s[j][m][1] = s[j][m][2] = s[j][m][3] = 0.0f;
            #pragma unroll
            for (int kc = 0; kc < 4; kc++)
                #pragma unroll
                for (int jp = 0; jp < 4; jp++) {
                    unsigned kf[4];
                    ldsm4(kf, kbuf + ((jp * 16 + brow) * KSTR + kc * 16 + bcol) * 2);
                    #pragma unroll
                    for (int m = 0; m < 2; m++) {
                        mma16(s[jp * 2][m],     qa[kc][m], kf[0], kf[1]);
                        mma16(s[jp * 2 + 1][m], qa[kc][m], kf[2], kf[3]);
                    }
                }

            // ---- No-max softmax in fp16x2: P = exp2(S + bias) ----
            float sum[4] = {0.0f, 0.0f, 0.0f, 0.0f};
            #pragma unroll
            for (int j = 0; j < 8; j++) {
                float b0v = __ldg(&bgh[j * 8 + 2 * tig]);
                float b1v = __ldg(&bgh[j * 8 + 2 * tig + 1]);
                #pragma unroll
                for (int m = 0; m < 2; m++) {
                    __half2 e0 = h2exp2(__floats2half2_rn(s[j][m][0] + b0v, s[j][m][1] + b1v));
                    __half2 e1 = h2exp2(__floats2half2_rn(s[j][m][2] + b0v, s[j][m][3] + b1v));
                    *(__half2*)&Pw[(m * 16 + g) * PSTR + j * 8 + 2 * tig]     = e0;
                    *(__half2*)&Pw[(m * 16 + g + 8) * PSTR + j * 8 + 2 * tig] = e1;
                    float2 f0 = __half22float2(e0);
                    float2 f1 = __half22float2(e1);
                    sum[m * 2]     += f0.x + f0.y;
                    sum[m * 2 + 1] += f1.x + f1.y;
                }
            }
            #pragma unroll
            for (int st = 0; st < 4; st++) {
                sum[st] += __shfl_xor_sync(0xffffffffu, sum[st], 1);
                sum[st] += __shfl_xor_sync(0xffffffffu, sum[st], 2);
                lr[st] += sum[st];
            }
            __syncwarp();

            // ---- O += P @ V ----
            #pragma unroll
            for (int kc = 0; kc < 4; kc++) {
                unsigned pa[2][4];
                #pragma unroll
                for (int m = 0; m < 2; m++)
                    ldsm4(pa[m], psb + ((m * 16 + arow) * PSTR + kc * 16 + acol) * 2);
                #pragma unroll
                for (int dp = 0; dp < 4; dp++) {
                    unsigned vf[4];
                    ldsm4t(vf, vbuf + ((kc * 16 + vrow) * VSTR + dp * 16 + vcol) * 2);
                    #pragma unroll
                    for (int m = 0; m < 2; m++) {
                        mma16(o[dp * 2][m],     pa[m], vf[0], vf[1]);
                        mma16(o[dp * 2 + 1][m], pa[m], vf[2], vf[3]);
                    }
                }
            }
            __syncwarp();
        }
        __syncthreads();   // K/V buffer reuse
    }

    // Epilogue: out[(t,b), h*64 + d] = O / l  (half)
    #pragma unroll
    for (int m = 0; m < 2; m++) {
        float i0 = (lr[m * 2] > 0.0f)     ? 1.0f / lr[m * 2]     : 0.0f;
        float i1 = (lr[m * 2 + 1] > 0.0f) ? 1.0f / lr[m * 2 + 1] : 0.0f;
        int t0 = qt0 + warp * 32 + m * 16 + g;
        int t1 = t0 + 8;
        __half* d0 = out + ((size_t)t0 * B_DIM + b) * E_DIM + h * 64;
        __half* d1 = out + ((size_t)t1 * B_DIM + b) * E_DIM + h * 64;
        #pragma unroll
        for (int dj = 0; dj < 8; dj++) {
            *(__half2*)&d0[dj * 8 + 2 * tig] =
                __floats2half2_rn(o[dj][m][0] * i0, o[dj][m][1] * i0);
            *(__half2*)&d1[dj * 8 + 2 * tig] =
                __floats2half2_rn(o[dj][m][2] * i1, o[dj][m][3] * i1);
        }
    }
}

// ---------------------------------------------------------------------------
extern "C" void kernel_launch(void* const* d_in, const int* in_sizes, int n_in,
                              void* d_out, int out_size)
{
    (void)in_sizes; (void)n_in; (void)out_size;
    const float* query = (const float*)d_in[0];
    const float* key   = (const float*)d_in[1];
    const float* value = (const float*)d_in[2];
    const unsigned char* mask = (const unsigned char*)d_in[3];
    const float* wq = (const float*)d_in[4];
    const float* bq = (const float*)d_in[5];
    const float* wk = (const float*)d_in[6];
    const float* bk = (const float*)d_in[7];
    const float* wv = (const float*)d_in[8];
    const float* bv = (const float*)d_in[9];
    const float* wo = (const float*)d_in[10];
    const float* bo = (const float*)d_in[11];
    float* out = (float*)d_out;

    __half *qb, *kb, *vb, *ab, *inh, *wh;
    float *bb;
    cudaGetSymbolAddress((void**)&qb, g_q);
    cudaGetSymbolAddress((void**)&kb, g_k);
    cudaGetSymbolAddress((void**)&vb, g_v);
    cudaGetSymbolAddress((void**)&ab, g_attn);
    cudaGetSymbolAddress((void**)&bb, g_bias);
    cudaGetSymbolAddress((void**)&inh, g_in_h);
    cudaGetSymbolAddress((void**)&wh, g_w_h);

    const int IN  = M_DIM * E_DIM;
    const int WSZ = E_DIM * E_DIM;

    static int smem_set = 0;
    const int gemm_smem = 3 * 2 * GSTAGEH * (int)sizeof(__half);   // 110592
    const int attn_smem = ATTN_SMEM_HALFS * (int)sizeof(__half);   // 110592
    if (!smem_set) {
        cudaFuncSetAttribute(gemm_kernel<0>, cudaFuncAttributeMaxDynamicSharedMemorySize, gemm_smem);
        cudaFuncSetAttribute(gemm_kernel<1>, cudaFuncAttributeMaxDynamicSharedMemorySize, gemm_smem);
        cudaFuncSetAttribute(attn_kernel, cudaFuncAttributeMaxDynamicSharedMemorySize, attn_smem);
        smem_set = 1;
    }

    tohalf_kernel<<<(3 * IN + 4 * WSZ) / 4 / 256, 256>>>(
        (const float4*)query, (const float4*)key, (const float4*)value,
        (const float4*)wq, (const float4*)wk, (const float4*)wv, (const float4*)wo,
        inh, wh);

    mask_bias_kernel<<<(B_DIM * T_DIM + 255) / 256, 256>>>(mask, bb);

    GemmArgs qkv;
    qkv.A[0] = inh;           qkv.A[1] = inh + IN;      qkv.A[2] = inh + 2 * IN;
    qkv.W[0] = wh;            qkv.W[1] = wh + WSZ;      qkv.W[2] = wh + 2 * WSZ;
    qkv.bias[0] = bq;         qkv.bias[1] = bk;         qkv.bias[2] = bv;
    qkv.out[0] = qb;          qkv.out[1] = kb;          qkv.out[2] = vb;
    qkv.scale[0] = 0.125f * 1.4426950408889634f;        // D^-0.5 * log2(e)
    qkv.scale[1] = 1.0f;      qkv.scale[2] = 1.0f;

    dim3 gqkv(E_DIM / 128, M_DIM / 128, 3);   // (8, 32, 3)
    gemm_kernel<0><<<gqkv, 128, gemm_smem>>>(qkv);

    dim3 gattn(T_DIM / 256, B_DIM * H_DIM);   // (8, 32)
    attn_kernel<<<gattn, 256, attn_smem>>>(qb, kb, vb, bb, ab);

    GemmArgs oargs;
    oargs.A[0] = ab;   oargs.W[0] = wh + 3 * WSZ;  oargs.bias[0] = bo;
    oargs.out[0] = out; oargs.scale[0] = 1.0f;
    oargs.A[1] = oargs.A[2] = ab; oargs.W[1] = oargs.W[2] = wh;
    oargs.bias[1] = oargs.bias[2] = bo; oargs.out[1] = oargs.out[2] = (void*)out;
    oargs.scale[1] = oargs.scale[2] = 1.0f;

    dim3 gop(E_DIM / 128, M_DIM / 128, 1);    // (8, 32)
    gemm_kernel<1><<<gop, 128, gemm_smem>>>(oargs);
}

// round 16
// speedup vs baseline: 1.0835x; 1.0835x over previous
#include <cuda_runtime.h>
#include <cuda_fp16.h>
#include <cstdint>

#define T_DIM 2048
#define B_DIM 2
#define E_DIM 1024
#define H_DIM 16
#define D_DIM 64
#define M_DIM (T_DIM * B_DIM)

__device__ __half g_q[B_DIM * H_DIM * T_DIM * D_DIM];
__device__ __half g_k[B_DIM * H_DIM * T_DIM * D_DIM];
__device__ __half g_v[B_DIM * H_DIM * T_DIM * D_DIM];
__device__ __half g_attn[T_DIM * B_DIM * E_DIM];
__device__ float  g_bias[B_DIM * T_DIM];
__device__ __half g_in_h[3 * M_DIM * E_DIM];
__device__ __half g_w_h[4 * E_DIM * E_DIM];

__device__ __forceinline__ float ex2f(float x) {
    float y;
    asm("ex2.approx.f32 %0, %1;" : "=f"(y) : "f"(x));
    return y;
}

__device__ __forceinline__ void cp16h(__half* smem, const __half* gmem) {
    unsigned s = (unsigned)__cvta_generic_to_shared(smem);
    asm volatile("cp.async.cg.shared.global [%0], [%1], 16;\n" :: "r"(s), "l"(gmem));
}
__device__ __forceinline__ void cp_commit() { asm volatile("cp.async.commit_group;\n"); }
template <int N> __device__ __forceinline__ void cp_wait() {
    asm volatile("cp.async.wait_group %0;\n" :: "n"(N));
}

__device__ __forceinline__ void mma16(float* d, const unsigned* a, unsigned b0, unsigned b1) {
    asm volatile(
        "mma.sync.aligned.m16n8k16.row.col.f32.f16.f16.f32 "
        "{%0,%1,%2,%3},{%4,%5,%6,%7},{%8,%9},{%0,%1,%2,%3};"
        : "+f"(d[0]), "+f"(d[1]), "+f"(d[2]), "+f"(d[3])
        : "r"(a[0]), "r"(a[1]), "r"(a[2]), "r"(a[3]), "r"(b0), "r"(b1));
}

__device__ __forceinline__ void ldsm4(unsigned* r, unsigned addr) {
    asm volatile("ldmatrix.sync.aligned.m8n8.x4.shared.b16 {%0,%1,%2,%3}, [%4];"
                 : "=r"(r[0]), "=r"(r[1]), "=r"(r[2]), "=r"(r[3]) : "r"(addr));
}
__device__ __forceinline__ void ldsm4t(unsigned* r, unsigned addr) {
    asm volatile("ldmatrix.sync.aligned.m8n8.x4.trans.shared.b16 {%0,%1,%2,%3}, [%4];"
                 : "=r"(r[0]), "=r"(r[1]), "=r"(r[2]), "=r"(r[3]) : "r"(addr));
}

// ---------------------------------------------------------------------------
__global__ void tohalf_kernel(const float4* __restrict__ q, const float4* __restrict__ k,
                              const float4* __restrict__ v, const float4* __restrict__ wq,
                              const float4* __restrict__ wk, const float4* __restrict__ wv,
                              const float4* __restrict__ wo, __half* __restrict__ din,
                              __half* __restrict__ dw)
{
    const int IN4 = M_DIM * E_DIM / 4;
    const int W4  = E_DIM * E_DIM / 4;
    int i = blockIdx.x * blockDim.x + threadIdx.x;
    const float4* s;
    __half* d;
    if (i < 3 * IN4) {
        s = (i < IN4) ? q + i : (i < 2 * IN4 ? k + (i - IN4) : v + (i - 2 * IN4));
        d = din + (size_t)i * 4;
    } else {
        int j = i - 3 * IN4;
        s = (j < W4) ? wq + j : j < 2 * W4 ? wk + (j - W4) : j < 3 * W4 ? wv + (j - 2 * W4)
                                                                        : wo + (j - 3 * W4);
        d = dw + (size_t)j * 4;
    }
    float4 x = *s;
    __half2 h01 = __floats2half2_rn(x.x, x.y);
    __half2 h23 = __floats2half2_rn(x.z, x.w);
    uint2 u;
    u.x = *(unsigned*)&h01;
    u.y = *(unsigned*)&h23;
    *(uint2*)d = u;
}

__global__ void mask_bias_kernel(const unsigned char* __restrict__ mask, float* __restrict__ bias) {
    int i = blockIdx.x * blockDim.x + threadIdx.x;
    if (i < B_DIM * T_DIM) bias[i] = mask[i] ? -1.4426950e30f : 0.0f;
}

// ---------------------------------------------------------------------------
// fp16 GEMM (R14): 128x128 block, 64x64 warp tile, BK=32, 3-stage cp.async,
// ldmatrix fragments, m16n8k16, fp32 accum.
// ---------------------------------------------------------------------------
struct GemmArgs {
    const __half* A[3];
    const __half* W[3];
    const float* bias[3];
    void* out[3];
    float scale[3];
};

#define GPADH   40
#define GSTAGEH (128 * GPADH)

template <int MODE>
__global__ __launch_bounds__(128, 2)
void gemm_kernel(GemmArgs args)
{
    extern __shared__ __half smh[];

    const int z    = (MODE == 0) ? blockIdx.z : 0;
    const __half* A = args.A[z];
    const __half* W = args.W[z];
    const float* bias = args.bias[z];
    const float scale = args.scale[z];

    const int tid  = threadIdx.x;
    const int warp = tid >> 5;
    const int lane = tid & 31;
    const int g    = lane >> 2;
    const int tig  = lane & 3;
    const int wm   = warp >> 1;
    const int wn   = warp & 1;
    const int row0 = blockIdx.y * 128;
    const int col0 = blockIdx.x * 128;

    const unsigned smb = (unsigned)__cvta_generic_to_shared(smh);
    const int arow = (lane & 15);
    const int acol = (lane >> 4) * 8;
    const int brow = (lane & 7) + (lane >> 4) * 8;
    const int bcol = ((lane >> 3) & 1) * 8;

    float acc[4][8][4];
    #pragma unroll
    for (int mi = 0; mi < 4; mi++)
        #pragma unroll
        for (int ni = 0; ni < 8; ni++)
            acc[mi][ni][0] = acc[mi][ni][1] = acc[mi][ni][2] = acc[mi][ni][3] = 0.0f;

    const __half* Agb = &A[(size_t)(row0 + tid) * 1024];
    const __half* Wgb = &W[(size_t)(col0 + tid) * 1024];

    auto stage = [&](int kt, int st) {
        __half* Ad = smh + st * 2 * GSTAGEH + tid * GPADH;
        __half* Bd = Ad + GSTAGEH;
        const int k0 = kt * 32;
        #pragma unroll
        for (int c = 0; c < 32; c += 8) {
            cp16h(Ad + c, Agb + k0 + c);
            cp16h(Bd + c, Wgb + k0 + c);
        }
        cp_commit();
    };

    auto compute = [&](int st) {
        const unsigned asb = smb + st * 2 * GSTAGEH * 2;
        const unsigned bsb = asb + GSTAGEH * 2;
        #pragma unroll
        for (int kc = 0; kc < 2; kc++) {
            unsigned af[4][4];
            unsigned bf[4][4];
            #pragma unroll
            for (int mi = 0; mi < 4; mi++)
                ldsm4(af[mi], asb + ((wm * 64 + mi * 16 + arow) * GPADH + kc * 16 + acol) * 2);
            #pragma unroll
            for (int np = 0; np < 4; np++)
                ldsm4(bf[np], bsb + ((wn * 64 + np * 16 + brow) * GPADH + kc * 16 + bcol) * 2);
            #pragma unroll
            for (int mi = 0; mi < 4; mi++)
                #pragma unroll
                for (int np = 0; np < 4; np++) {
                    mma16(acc[mi][np * 2],     af[mi], bf[np][0], bf[np][1]);
                    mma16(acc[mi][np * 2 + 1], af[mi], bf[np][2], bf[np][3]);
                }
        }
    };

    const int NT = 1024 / 32;
    stage(0, 0);
    stage(1, 1);
    for (int t = 0; t < NT; t++) {
        if (t + 1 < NT) cp_wait<1>();
        else            cp_wait<0>();
        __syncthreads();
        if (t + 2 < NT) stage(t + 2, (t + 2) % 3);
        compute(t % 3);
    }

    float bvals[8][2];
    #pragma unroll
    for (int ni = 0; ni < 8; ni++) {
        int c = col0 + wn * 64 + ni * 8 + 2 * tig;
        bvals[ni][0] = __ldg(&bias[c]);
        bvals[ni][1] = __ldg(&bias[c + 1]);
    }
    #pragma unroll
    for (int mi = 0; mi < 4; mi++) {
        #pragma unroll
        for (int rr = 0; rr < 2; rr++) {
            int r = row0 + wm * 64 + mi * 16 + g + rr * 8;
            #pragma unroll
            for (int ni = 0; ni < 8; ni++) {
                int o = col0 + wn * 64 + ni * 8 + 2 * tig;
                float v0 = (acc[mi][ni][rr * 2]     + bvals[ni][0]) * scale;
                float v1 = (acc[mi][ni][rr * 2 + 1] + bvals[ni][1]) * scale;
                if (MODE == 0) {
                    __half* out = (__half*)args.out[z];
                    int t = r >> 1, b = r & 1;
                    int h = o >> 6, d = o & 63;
                    *(__half2*)&out[(((size_t)(b * H_DIM + h)) * T_DIM + t) * D_DIM + d] =
                        __floats2half2_rn(v0, v1);
                } else {
                    float* out = (float*)args.out[z];
                    *(float2*)&out[(size_t)r * E_DIM + o] = make_float2(v0, v1);
                }
            }
        }
    }
}

// ---------------------------------------------------------------------------
// Flash attention fp16 v5: 128 threads (4 warps x 32 q = 128 q/block),
// 2 CTAs/SM for cross-CTA latency overlap. 64-key tiles x 32 iters,
// double-buffered K/V, Q frags in regs, ldmatrix K/P/V, no-max fp32 softmax.
// ---------------------------------------------------------------------------
#define KSTR 72
#define VSTR 72
#define PSTR 72

#define ATTN_SMEM_HALFS (2 * 64 * KSTR + 2 * 64 * VSTR + 4 * 32 * PSTR)

__global__ __launch_bounds__(128, 2)
void attn_kernel(const __half* __restrict__ q, const __half* __restrict__ k,
                 const __half* __restrict__ v, const float* __restrict__ biasg,
                 __half* __restrict__ out)
{
    extern __shared__ __half smh[];
    __half* Kst = smh;                         // 2 x 64 x KSTR
    __half* Vst = Kst + 2 * 64 * KSTR;         // 2 x 64 x VSTR
    __half* Ps  = Vst + 2 * 64 * VSTR;         // 4 warps x 32 x PSTR

    const int tid  = threadIdx.x;
    const int warp = tid >> 5;
    const int lane = tid & 31;
    const int g    = lane >> 2;
    const int tig  = lane & 3;
    const int qt0  = blockIdx.x * 128;
    const int bh   = blockIdx.y;
    const int b    = bh >> 4;
    const int h    = bh & 15;

    const __half* qb = q + (size_t)bh * T_DIM * D_DIM;
    const __half* kb = k + (size_t)bh * T_DIM * D_DIM;
    const __half* vb = v + (size_t)bh * T_DIM * D_DIM;
    const float* bg = biasg + (size_t)b * T_DIM;
    __half* Pw = Ps + warp * 32 * PSTR;

    const unsigned ksb = (unsigned)__cvta_generic_to_shared(Kst);
    const unsigned vsb = (unsigned)__cvta_generic_to_shared(Vst);
    const unsigned psb = (unsigned)__cvta_generic_to_shared(Pw);

    const int arow = (lane & 15);
    const int acol = (lane >> 4) * 8;
    const int brow = (lane & 7) + (lane >> 4) * 8;
    const int bcol = ((lane >> 3) & 1) * 8;
    const int vrow = (lane & 7) + ((lane >> 3) & 1) * 8;
    const int vcol = (lane >> 4) * 8;

    // Q A-fragments from gmem (once per block)
    unsigned qa[4][2][4];
    {
        const __half* qw = qb + (size_t)(qt0 + warp * 32) * 64;
        #pragma unroll
        for (int kc = 0; kc < 4; kc++)
            #pragma unroll
            for (int m = 0; m < 2; m++) {
                int r0 = m * 16 + g, r1 = r0 + 8;
                qa[kc][m][0] = *(const unsigned*)&qw[r0 * 64 + kc * 16 + 2 * tig];
                qa[kc][m][1] = *(const unsigned*)&qw[r1 * 64 + kc * 16 + 2 * tig];
                qa[kc][m][2] = *(const unsigned*)&qw[r0 * 64 + kc * 16 + 2 * tig + 8];
                qa[kc][m][3] = *(const unsigned*)&qw[r1 * 64 + kc * 16 + 2 * tig + 8];
            }
    }

    float o[8][2][4];
    #pragma unroll
    for (int dj = 0; dj < 8; dj++)
        #pragma unroll
        for (int m = 0; m < 2; m++)
            o[dj][m][0] = o[dj][m][1] = o[dj][m][2] = o[dj][m][3] = 0.0f;
    float lr[4] = {0.0f, 0.0f, 0.0f, 0.0f};

    auto stageKV = [&](int it, int buf) {
        const int s0 = it * 64;
        __half* Kd = Kst + buf * 64 * KSTR;
        __half* Vd = Vst + buf * 64 * VSTR;
        #pragma unroll
        for (int i = 0; i < 4; i++) {
            int idx = tid + i * 128;           // 0..511
            int r = idx >> 3, c = (idx & 7) * 8;
            cp16h(&Kd[r * KSTR + c], &kb[(size_t)(s0 + r) * 64 + c]);
            cp16h(&Vd[r * VSTR + c], &vb[(size_t)(s0 + r) * 64 + c]);
        }
        cp_commit();
    };

    stageKV(0, 0);
    for (int it = 0; it < 32; it++) {
        cp_wait<0>();
        __syncthreads();
        if (it + 1 < 32) stageKV(it + 1, (it + 1) & 1);

        const unsigned kbuf = ksb + (it & 1) * 64 * KSTR * 2;
        const unsigned vbuf = vsb + (it & 1) * 64 * VSTR * 2;

        // ---- S = Q @ K^T (32q x 64k per warp), K frags via ldmatrix ----
        float s[8][2][4];
        #pragma unroll
        for (int j = 0; j < 8; j++)
            #pragma unroll
            for (int m = 0; m < 2; m++)
                s[j][m][0] = s[j][m][1] = s[j][m][2] = s[j][m][3] = 0.0f;
        #pragma unroll
        for (int kc = 0; kc < 4; kc++)
            #pragma unroll
            for (int jp = 0; jp < 4; jp++) {
                unsigned kf[4];
                ldsm4(kf, kbuf + ((jp * 16 + brow) * KSTR + kc * 16 + bcol) * 2);
                #pragma unroll
                for (int m = 0; m < 2; m++) {
                    mma16(s[jp * 2][m],     qa[kc][m], kf[0], kf[1]);
                    mma16(s[jp * 2 + 1][m], qa[kc][m], kf[2], kf[3]);
                }
            }

        // ---- No-max softmax: P = exp2(S + bias); l += sum ----
        float sum[4] = {0.0f, 0.0f, 0.0f, 0.0f};
        #pragma unroll
        for (int j = 0; j < 8; j++) {
            float b0v = __ldg(&bg[it * 64 + j * 8 + 2 * tig]);
            float b1v = __ldg(&bg[it * 64 + j * 8 + 2 * tig + 1]);
            #pragma unroll
            for (int m = 0; m < 2; m++) {
                s[j][m][0] = ex2f(s[j][m][0] + b0v); sum[m * 2]     += s[j][m][0];
                s[j][m][1] = ex2f(s[j][m][1] + b1v); sum[m * 2]     += s[j][m][1];
                s[j][m][2] = ex2f(s[j][m][2] + b0v); sum[m * 2 + 1] += s[j][m][2];
                s[j][m][3] = ex2f(s[j][m][3] + b1v); sum[m * 2 + 1] += s[j][m][3];
            }
        }
        #pragma unroll
        for (int st = 0; st < 4; st++) {
            sum[st] += __shfl_xor_sync(0xffffffffu, sum[st], 1);
            sum[st] += __shfl_xor_sync(0xffffffffu, sum[st], 2);
            lr[st] += sum[st];
        }

        // ---- P -> half smem ----
        #pragma unroll
        for (int j = 0; j < 8; j++)
            #pragma unroll
            for (int m = 0; m < 2; m++) {
                *(__half2*)&Pw[(m * 16 + g) * PSTR + j * 8 + 2 * tig] =
                    __floats2half2_rn(s[j][m][0], s[j][m][1]);
                *(__half2*)&Pw[(m * 16 + g + 8) * PSTR + j * 8 + 2 * tig] =
                    __floats2half2_rn(s[j][m][2], s[j][m][3]);
            }
        __syncwarp();

        // ---- O += P @ V: P frags via ldmatrix, V via ldmatrix.trans ----
        #pragma unroll
        for (int kc = 0; kc < 4; kc++) {
            unsigned pa[2][4];
            #pragma unroll
            for (int m = 0; m < 2; m++)
                ldsm4(pa[m], psb + ((m * 16 + arow) * PSTR + kc * 16 + acol) * 2);
            #pragma unroll
            for (int dp = 0; dp < 4; dp++) {
                unsigned vf[4];
                ldsm4t(vf, vbuf + ((kc * 16 + vrow) * VSTR + dp * 16 + vcol) * 2);
                #pragma unroll
                for (int m = 0; m < 2; m++) {
                    mma16(o[dp * 2][m],     pa[m], vf[0], vf[1]);
                    mma16(o[dp * 2 + 1][m], pa[m], vf[2], vf[3]);
                }
            }
        }
        __syncthreads();   // K/V buffer + Pw reuse
    }

    // Epilogue: out[(t,b), h*64 + d] = O / l  (half)
    #pragma unroll
    for (int m = 0; m < 2; m++) {
        float i0 = (lr[m * 2] > 0.0f)     ? 1.0f / lr[m * 2]     : 0.0f;
        float i1 = (lr[m * 2 + 1] > 0.0f) ? 1.0f / lr[m * 2 + 1] : 0.0f;
        int t0 = qt0 + warp * 32 + m * 16 + g;
        int t1 = t0 + 8;
        __half* d0 = out + ((size_t)t0 * B_DIM + b) * E_DIM + h * 64;
        __half* d1 = out + ((size_t)t1 * B_DIM + b) * E_DIM + h * 64;
        #pragma unroll
        for (int dj = 0; dj < 8; dj++) {
            *(__half2*)&d0[dj * 8 + 2 * tig] =
                __floats2half2_rn(o[dj][m][0] * i0, o[dj][m][1] * i0);
            *(__half2*)&d1[dj * 8 + 2 * tig] =
                __floats2half2_rn(o[dj][m][2] * i1, o[dj][m][3] * i1);
        }
    }
}

// ---------------------------------------------------------------------------
extern "C" void kernel_launch(void* const* d_in, const int* in_sizes, int n_in,
                              void* d_out, int out_size)
{
    (void)in_sizes; (void)n_in; (void)out_size;
    const float* query = (const float*)d_in[0];
    const float* key   = (const float*)d_in[1];
    const float* value = (const float*)d_in[2];
    const unsigned char* mask = (const unsigned char*)d_in[3];
    const float* wq = (const float*)d_in[4];
    const float* bq = (const float*)d_in[5];
    const float* wk = (const float*)d_in[6];
    const float* bk = (const float*)d_in[7];
    const float* wv = (const float*)d_in[8];
    const float* bv = (const float*)d_in[9];
    const float* wo = (const float*)d_in[10];
    const float* bo = (const float*)d_in[11];
    float* out = (float*)d_out;

    __half *qb, *kb, *vb, *ab, *inh, *wh;
    float *bb;
    cudaGetSymbolAddress((void**)&qb, g_q);
    cudaGetSymbolAddress((void**)&kb, g_k);
    cudaGetSymbolAddress((void**)&vb, g_v);
    cudaGetSymbolAddress((void**)&ab, g_attn);
    cudaGetSymbolAddress((void**)&bb, g_bias);
    cudaGetSymbolAddress((void**)&inh, g_in_h);
    cudaGetSymbolAddress((void**)&wh, g_w_h);

    const int IN  = M_DIM * E_DIM;
    const int WSZ = E_DIM * E_DIM;

    static int smem_set = 0;
    const int gemm_smem = 3 * 2 * GSTAGEH * (int)sizeof(__half);   // 61440
    const int attn_smem = ATTN_SMEM_HALFS * (int)sizeof(__half);   // 55296
    if (!smem_set) {
        cudaFuncSetAttribute(gemm_kernel<0>, cudaFuncAttributeMaxDynamicSharedMemorySize, gemm_smem);
        cudaFuncSetAttribute(gemm_kernel<1>, cudaFuncAttributeMaxDynamicSharedMemorySize, gemm_smem);
        cudaFuncSetAttribute(attn_kernel, cudaFuncAttributeMaxDynamicSharedMemorySize, attn_smem);
        smem_set = 1;
    }

    tohalf_kernel<<<(3 * IN + 4 * WSZ) / 4 / 256, 256>>>(
        (const float4*)query, (const float4*)key, (const float4*)value,
        (const float4*)wq, (const float4*)wk, (const float4*)wv, (const float4*)wo,
        inh, wh);

    mask_bias_kernel<<<(B_DIM * T_DIM + 255) / 256, 256>>>(mask, bb);

    GemmArgs qkv;
    qkv.A[0] = inh;           qkv.A[1] = inh + IN;      qkv.A[2] = inh + 2 * IN;
    qkv.W[0] = wh;            qkv.W[1] = wh + WSZ;      qkv.W[2] = wh + 2 * WSZ;
    qkv.bias[0] = bq;         qkv.bias[1] = bk;         qkv.bias[2] = bv;
    qkv.out[0] = qb;          qkv.out[1] = kb;          qkv.out[2] = vb;
    qkv.scale[0] = 0.125f * 1.4426950408889634f;        // D^-0.5 * log2(e)
    qkv.scale[1] = 1.0f;      qkv.scale[2] = 1.0f;

    dim3 gqkv(E_DIM / 128, M_DIM / 128, 3);   // (8, 32, 3)
    gemm_kernel<0><<<gqkv, 128, gemm_smem>>>(qkv);

    dim3 gattn(T_DIM / 128, B_DIM * H_DIM);   // (16, 32) = 512 CTAs
    attn_kernel<<<gattn, 128, attn_smem>>>(qb, kb, vb, bb, ab);

    GemmArgs oargs;
    oargs.A[0] = ab;   oargs.W[0] = wh + 3 * WSZ;  oargs.bias[0] = bo;
    oargs.out[0] = out; oargs.scale[0] = 1.0f;
    oargs.A[1] = oargs.A[2] = ab; oargs.W[1] = oargs.W[2] = wh;
    oargs.bias[1] = oargs.bias[2] = bo; oargs.out[1] = oargs.out[2] = (void*)out;
    oargs.scale[1] = oargs.scale[2] = 1.0f;

    dim3 gop(E_DIM / 128, M_DIM / 128, 1);    // (8, 32)
    gemm_kernel<1><<<gop, 128, gemm_smem>>>(oargs);
}

// round 17
// speedup vs baseline: 1.3227x; 1.2207x over previous
#include <cuda_runtime.h>
#include <cuda_fp16.h>
#include <cstdint>

#define T_DIM 2048
#define B_DIM 2
#define E_DIM 1024
#define H_DIM 16
#define D_DIM 64
#define M_DIM (T_DIM * B_DIM)

__device__ __half g_q[B_DIM * H_DIM * T_DIM * D_DIM];
__device__ __half g_k[B_DIM * H_DIM * T_DIM * D_DIM];
__device__ __half g_v[B_DIM * H_DIM * T_DIM * D_DIM];
__device__ __half g_attn[T_DIM * B_DIM * E_DIM];
__device__ float  g_bias[B_DIM * T_DIM];
__device__ __half g_in_h[3 * M_DIM * E_DIM];
__device__ __half g_w_h[4 * E_DIM * E_DIM];

__device__ __forceinline__ float ex2f(float x) {
    float y;
    asm("ex2.approx.f32 %0, %1;" : "=f"(y) : "f"(x));
    return y;
}

__device__ __forceinline__ void cp16h(__half* smem, const __half* gmem) {
    unsigned s = (unsigned)__cvta_generic_to_shared(smem);
    asm volatile("cp.async.cg.shared.global [%0], [%1], 16;\n" :: "r"(s), "l"(gmem));
}
__device__ __forceinline__ void cp_commit() { asm volatile("cp.async.commit_group;\n"); }
template <int N> __device__ __forceinline__ void cp_wait() {
    asm volatile("cp.async.wait_group %0;\n" :: "n"(N));
}

__device__ __forceinline__ void mma16(float* d, const unsigned* a, unsigned b0, unsigned b1) {
    asm volatile(
        "mma.sync.aligned.m16n8k16.row.col.f32.f16.f16.f32 "
        "{%0,%1,%2,%3},{%4,%5,%6,%7},{%8,%9},{%0,%1,%2,%3};"
        : "+f"(d[0]), "+f"(d[1]), "+f"(d[2]), "+f"(d[3])
        : "r"(a[0]), "r"(a[1]), "r"(a[2]), "r"(a[3]), "r"(b0), "r"(b1));
}

__device__ __forceinline__ void ldsm4(unsigned* r, unsigned addr) {
    asm volatile("ldmatrix.sync.aligned.m8n8.x4.shared.b16 {%0,%1,%2,%3}, [%4];"
                 : "=r"(r[0]), "=r"(r[1]), "=r"(r[2]), "=r"(r[3]) : "r"(addr));
}
__device__ __forceinline__ void ldsm4t(unsigned* r, unsigned addr) {
    asm volatile("ldmatrix.sync.aligned.m8n8.x4.trans.shared.b16 {%0,%1,%2,%3}, [%4];"
                 : "=r"(r[0]), "=r"(r[1]), "=r"(r[2]), "=r"(r[3]) : "r"(addr));
}

// ---------------------------------------------------------------------------
__global__ void tohalf_kernel(const float4* __restrict__ q, const float4* __restrict__ k,
                              const float4* __restrict__ v, const float4* __restrict__ wq,
                              const float4* __restrict__ wk, const float4* __restrict__ wv,
                              const float4* __restrict__ wo, __half* __restrict__ din,
                              __half* __restrict__ dw)
{
    const int IN4 = M_DIM * E_DIM / 4;
    const int W4  = E_DIM * E_DIM / 4;
    int i = blockIdx.x * blockDim.x + threadIdx.x;
    const float4* s;
    __half* d;
    if (i < 3 * IN4) {
        s = (i < IN4) ? q + i : (i < 2 * IN4 ? k + (i - IN4) : v + (i - 2 * IN4));
        d = din + (size_t)i * 4;
    } else {
        int j = i - 3 * IN4;
        s = (j < W4) ? wq + j : j < 2 * W4 ? wk + (j - W4) : j < 3 * W4 ? wv + (j - 2 * W4)
                                                                        : wo + (j - 3 * W4);
        d = dw + (size_t)j * 4;
    }
    float4 x = *s;
    __half2 h01 = __floats2half2_rn(x.x, x.y);
    __half2 h23 = __floats2half2_rn(x.z, x.w);
    uint2 u;
    u.x = *(unsigned*)&h01;
    u.y = *(unsigned*)&h23;
    *(uint2*)d = u;
}

__global__ void mask_bias_kernel(const unsigned char* __restrict__ mask, float* __restrict__ bias) {
    int i = blockIdx.x * blockDim.x + threadIdx.x;
    if (i < B_DIM * T_DIM) bias[i] = mask[i] ? -1.4426950e30f : 0.0f;
}

// ---------------------------------------------------------------------------
// fp16 GEMM v3: 128x128 block, 256 threads (8 warps, 2x4 grid, warp tile
// 64x32), BK=32, 3-stage cp.async, ldmatrix fragments, m16n8k16, fp32 accum.
// acc=64 regs/thread -> ~128 total -> 2 CTAs/SM = 16 warps/SM.
// ---------------------------------------------------------------------------
struct GemmArgs {
    const __half* A[3];
    const __half* W[3];
    const float* bias[3];
    void* out[3];
    float scale[3];
};

#define GPADH   40
#define GSTAGEH (128 * GPADH)

template <int MODE>
__global__ __launch_bounds__(256, 2)
void gemm_kernel(GemmArgs args)
{
    extern __shared__ __half smh[];

    const int z    = (MODE == 0) ? blockIdx.z : 0;
    const __half* A = args.A[z];
    const __half* W = args.W[z];
    const float* bias = args.bias[z];
    const float scale = args.scale[z];

    const int tid  = threadIdx.x;
    const int warp = tid >> 5;
    const int lane = tid & 31;
    const int g    = lane >> 2;
    const int tig  = lane & 3;
    const int wm   = warp >> 2;          // 0..1 : 64 rows each
    const int wn   = warp & 3;           // 0..3 : 32 cols each
    const int row0 = blockIdx.y * 128;
    const int col0 = blockIdx.x * 128;

    const unsigned smb = (unsigned)__cvta_generic_to_shared(smh);
    const int arow = (lane & 15);
    const int acol = (lane >> 4) * 8;
    const int brow = (lane & 7) + (lane >> 4) * 8;
    const int bcol = ((lane >> 3) & 1) * 8;

    float acc[4][4][4];                  // mi(16-row) x ni(8-col) = 64 regs
    #pragma unroll
    for (int mi = 0; mi < 4; mi++)
        #pragma unroll
        for (int ni = 0; ni < 4; ni++)
            acc[mi][ni][0] = acc[mi][ni][1] = acc[mi][ni][2] = acc[mi][ni][3] = 0.0f;

    // staging: 512 cp16 for A + 512 for B over 256 threads -> 2 each per mat
    const int sr  = tid >> 2;            // 0..63
    const int sc  = (tid & 3) * 8;       // 0,8,16,24
    const __half* Agb = &A[(size_t)row0 * 1024];
    const __half* Wgb = &W[(size_t)col0 * 1024];

    auto stage = [&](int kt, int st) {
        __half* Ad = smh + st * 2 * GSTAGEH;
        __half* Bd = Ad + GSTAGEH;
        const int k0 = kt * 32;
        #pragma unroll
        for (int i = 0; i < 2; i++) {
            int r = sr + i * 64;
            cp16h(&Ad[r * GPADH + sc], Agb + (size_t)r * 1024 + k0 + sc);
            cp16h(&Bd[r * GPADH + sc], Wgb + (size_t)r * 1024 + k0 + sc);
        }
        cp_commit();
    };

    auto compute = [&](int st) {
        const unsigned asb = smb + st * 2 * GSTAGEH * 2;
        const unsigned bsb = asb + GSTAGEH * 2;
        #pragma unroll
        for (int kc = 0; kc < 2; kc++) {
            unsigned af[4][4];
            unsigned bf[2][4];
            #pragma unroll
            for (int mi = 0; mi < 4; mi++)
                ldsm4(af[mi], asb + ((wm * 64 + mi * 16 + arow) * GPADH + kc * 16 + acol) * 2);
            #pragma unroll
            for (int np = 0; np < 2; np++)
                ldsm4(bf[np], bsb + ((wn * 32 + np * 16 + brow) * GPADH + kc * 16 + bcol) * 2);
            #pragma unroll
            for (int mi = 0; mi < 4; mi++)
                #pragma unroll
                for (int np = 0; np < 2; np++) {
                    mma16(acc[mi][np * 2],     af[mi], bf[np][0], bf[np][1]);
                    mma16(acc[mi][np * 2 + 1], af[mi], bf[np][2], bf[np][3]);
                }
        }
    };

    const int NT = 1024 / 32;
    stage(0, 0);
    stage(1, 1);
    for (int t = 0; t < NT; t++) {
        if (t + 1 < NT) cp_wait<1>();
        else            cp_wait<0>();
        __syncthreads();
        if (t + 2 < NT) stage(t + 2, (t + 2) % 3);
        compute(t % 3);
    }

    float bvals[4][2];
    #pragma unroll
    for (int ni = 0; ni < 4; ni++) {
        int c = col0 + wn * 32 + ni * 8 + 2 * tig;
        bvals[ni][0] = __ldg(&bias[c]);
        bvals[ni][1] = __ldg(&bias[c + 1]);
    }
    #pragma unroll
    for (int mi = 0; mi < 4; mi++) {
        #pragma unroll
        for (int rr = 0; rr < 2; rr++) {
            int r = row0 + wm * 64 + mi * 16 + g + rr * 8;   // = t*B + b
            #pragma unroll
            for (int ni = 0; ni < 4; ni++) {
                int o = col0 + wn * 32 + ni * 8 + 2 * tig;
                float v0 = (acc[mi][ni][rr * 2]     + bvals[ni][0]) * scale;
                float v1 = (acc[mi][ni][rr * 2 + 1] + bvals[ni][1]) * scale;
                if (MODE == 0) {
                    __half* out = (__half*)args.out[z];
                    int t = r >> 1, b = r & 1;
                    int h = o >> 6, d = o & 63;
                    *(__half2*)&out[(((size_t)(b * H_DIM + h)) * T_DIM + t) * D_DIM + d] =
                        __floats2half2_rn(v0, v1);
                } else {
                    float* out = (float*)args.out[z];
                    *(float2*)&out[(size_t)r * E_DIM + o] = make_float2(v0, v1);
                }
            }
        }
    }
}

// ---------------------------------------------------------------------------
// Flash attention fp16 v5 (R16, unchanged): 128 threads (4 warps x 32 q),
// 2 CTAs/SM cross-CTA overlap, 64-key tiles x 32 iters, double-buffered K/V,
// Q frags in regs, ldmatrix K/P/V, no-max fp32 softmax.
// ---------------------------------------------------------------------------
#define KSTR 72
#define VSTR 72
#define PSTR 72

#define ATTN_SMEM_HALFS (2 * 64 * KSTR + 2 * 64 * VSTR + 4 * 32 * PSTR)

__global__ __launch_bounds__(128, 2)
void attn_kernel(const __half* __restrict__ q, const __half* __restrict__ k,
                 const __half* __restrict__ v, const float* __restrict__ biasg,
                 __half* __restrict__ out)
{
    extern __shared__ __half smh[];
    __half* Kst = smh;
    __half* Vst = Kst + 2 * 64 * KSTR;
    __half* Ps  = Vst + 2 * 64 * VSTR;

    const int tid  = threadIdx.x;
    const int warp = tid >> 5;
    const int lane = tid & 31;
    const int g    = lane >> 2;
    const int tig  = lane & 3;
    const int qt0  = blockIdx.x * 128;
    const int bh   = blockIdx.y;
    const int b    = bh >> 4;
    const int h    = bh & 15;

    const __half* qb = q + (size_t)bh * T_DIM * D_DIM;
    const __half* kb = k + (size_t)bh * T_DIM * D_DIM;
    const __half* vb = v + (size_t)bh * T_DIM * D_DIM;
    const float* bg = biasg + (size_t)b * T_DIM;
    __half* Pw = Ps + warp * 32 * PSTR;

    const unsigned ksb = (unsigned)__cvta_generic_to_shared(Kst);
    const unsigned vsb = (unsigned)__cvta_generic_to_shared(Vst);
    const unsigned psb = (unsigned)__cvta_generic_to_shared(Pw);

    const int arow = (lane & 15);
    const int acol = (lane >> 4) * 8;
    const int brow = (lane & 7) + (lane >> 4) * 8;
    const int bcol = ((lane >> 3) & 1) * 8;
    const int vrow = (lane & 7) + ((lane >> 3) & 1) * 8;
    const int vcol = (lane >> 4) * 8;

    unsigned qa[4][2][4];
    {
        const __half* qw = qb + (size_t)(qt0 + warp * 32) * 64;
        #pragma unroll
        for (int kc = 0; kc < 4; kc++)
            #pragma unroll
            for (int m = 0; m < 2; m++) {
                int r0 = m * 16 + g, r1 = r0 + 8;
                qa[kc][m][0] = *(const unsigned*)&qw[r0 * 64 + kc * 16 + 2 * tig];
                qa[kc][m][1] = *(const unsigned*)&qw[r1 * 64 + kc * 16 + 2 * tig];
                qa[kc][m][2] = *(const unsigned*)&qw[r0 * 64 + kc * 16 + 2 * tig + 8];
                qa[kc][m][3] = *(const unsigned*)&qw[r1 * 64 + kc * 16 + 2 * tig + 8];
            }
    }

    float o[8][2][4];
    #pragma unroll
    for (int dj = 0; dj < 8; dj++)
        #pragma unroll
        for (int m = 0; m < 2; m++)
            o[dj][m][0] = o[dj][m][1] = o[dj][m][2] = o[dj][m][3] = 0.0f;
    float lr[4] = {0.0f, 0.0f, 0.0f, 0.0f};

    auto stageKV = [&](int it, int buf) {
        const int s0 = it * 64;
        __half* Kd = Kst + buf * 64 * KSTR;
        __half* Vd = Vst + buf * 64 * VSTR;
        #pragma unroll
        for (int i = 0; i < 4; i++) {
            int idx = tid + i * 128;
            int r = idx >> 3, c = (idx & 7) * 8;
            cp16h(&Kd[r * KSTR + c], &kb[(size_t)(s0 + r) * 64 + c]);
            cp16h(&Vd[r * VSTR + c], &vb[(size_t)(s0 + r) * 64 + c]);
        }
        cp_commit();
    };

    stageKV(0, 0);
    for (int it = 0; it < 32; it++) {
        cp_wait<0>();
        __syncthreads();
        if (it + 1 < 32) stageKV(it + 1, (it + 1) & 1);

        const unsigned kbuf = ksb + (it & 1) * 64 * KSTR * 2;
        const unsigned vbuf = vsb + (it & 1) * 64 * VSTR * 2;

        float s[8][2][4];
        #pragma unroll
        for (int j = 0; j < 8; j++)
            #pragma unroll
            for (int m = 0; m < 2; m++)
                s[j][m][0] = s[j][m][1] = s[j][m][2] = s[j][m][3] = 0.0f;
        #pragma unroll
        for (int kc = 0; kc < 4; kc++)
            #pragma unroll
            for (int jp = 0; jp < 4; jp++) {
                unsigned kf[4];
                ldsm4(kf, kbuf + ((jp * 16 + brow) * KSTR + kc * 16 + bcol) * 2);
                #pragma unroll
                for (int m = 0; m < 2; m++) {
                    mma16(s[jp * 2][m],     qa[kc][m], kf[0], kf[1]);
                    mma16(s[jp * 2 + 1][m], qa[kc][m], kf[2], kf[3]);
                }
            }

        float sum[4] = {0.0f, 0.0f, 0.0f, 0.0f};
        #pragma unroll
        for (int j = 0; j < 8; j++) {
            float b0v = __ldg(&bg[it * 64 + j * 8 + 2 * tig]);
            float b1v = __ldg(&bg[it * 64 + j * 8 + 2 * tig + 1]);
            #pragma unroll
            for (int m = 0; m < 2; m++) {
                s[j][m][0] = ex2f(s[j][m][0] + b0v); sum[m * 2]     += s[j][m][0];
                s[j][m][1] = ex2f(s[j][m][1] + b1v); sum[m * 2]     += s[j][m][1];
                s[j][m][2] = ex2f(s[j][m][2] + b0v); sum[m * 2 + 1] += s[j][m][2];
                s[j][m][3] = ex2f(s[j][m][3] + b1v); sum[m * 2 + 1] += s[j][m][3];
            }
        }
        #pragma unroll
        for (int st = 0; st < 4; st++) {
            sum[st] += __shfl_xor_sync(0xffffffffu, sum[st], 1);
            sum[st] += __shfl_xor_sync(0xffffffffu, sum[st], 2);
            lr[st] += sum[st];
        }

        #pragma unroll
        for (int j = 0; j < 8; j++)
            #pragma unroll
            for (int m = 0; m < 2; m++) {
                *(__half2*)&Pw[(m * 16 + g) * PSTR + j * 8 + 2 * tig] =
                    __floats2half2_rn(s[j][m][0], s[j][m][1]);
                *(__half2*)&Pw[(m * 16 + g + 8) * PSTR + j * 8 + 2 * tig] =
                    __floats2half2_rn(s[j][m][2], s[j][m][3]);
            }
        __syncwarp();

        #pragma unroll
        for (int kc = 0; kc < 4; kc++) {
            unsigned pa[2][4];
            #pragma unroll
            for (int m = 0; m < 2; m++)
                ldsm4(pa[m], psb + ((m * 16 + arow) * PSTR + kc * 16 + acol) * 2);
            #pragma unroll
            for (int dp = 0; dp < 4; dp++) {
                unsigned vf[4];
                ldsm4t(vf, vbuf + ((kc * 16 + vrow) * VSTR + dp * 16 + vcol) * 2);
                #pragma unroll
                for (int m = 0; m < 2; m++) {
                    mma16(o[dp * 2][m],     pa[m], vf[0], vf[1]);
                    mma16(o[dp * 2 + 1][m], pa[m], vf[2], vf[3]);
                }
            }
        }
        __syncthreads();
    }

    #pragma unroll
    for (int m = 0; m < 2; m++) {
        float i0 = (lr[m * 2] > 0.0f)     ? 1.0f / lr[m * 2]     : 0.0f;
        float i1 = (lr[m * 2 + 1] > 0.0f) ? 1.0f / lr[m * 2 + 1] : 0.0f;
        int t0 = qt0 + warp * 32 + m * 16 + g;
        int t1 = t0 + 8;
        __half* d0 = out + ((size_t)t0 * B_DIM + b) * E_DIM + h * 64;
        __half* d1 = out + ((size_t)t1 * B_DIM + b) * E_DIM + h * 64;
        #pragma unroll
        for (int dj = 0; dj < 8; dj++) {
            *(__half2*)&d0[dj * 8 + 2 * tig] =
                __floats2half2_rn(o[dj][m][0] * i0, o[dj][m][1] * i0);
            *(__half2*)&d1[dj * 8 + 2 * tig] =
                __floats2half2_rn(o[dj][m][2] * i1, o[dj][m][3] * i1);
        }
    }
}

// ---------------------------------------------------------------------------
extern "C" void kernel_launch(void* const* d_in, const int* in_sizes, int n_in,
                              void* d_out, int out_size)
{
    (void)in_sizes; (void)n_in; (void)out_size;
    const float* query = (const float*)d_in[0];
    const float* key   = (const float*)d_in[1];
    const float* value = (const float*)d_in[2];
    const unsigned char* mask = (const unsigned char*)d_in[3];
    const float* wq = (const float*)d_in[4];
    const float* bq = (const float*)d_in[5];
    const float* wk = (const float*)d_in[6];
    const float* bk = (const float*)d_in[7];
    const float* wv = (const float*)d_in[8];
    const float* bv = (const float*)d_in[9];
    const float* wo = (const float*)d_in[10];
    const float* bo = (const float*)d_in[11];
    float* out = (float*)d_out;

    __half *qb, *kb, *vb, *ab, *inh, *wh;
    float *bb;
    cudaGetSymbolAddress((void**)&qb, g_q);
    cudaGetSymbolAddress((void**)&kb, g_k);
    cudaGetSymbolAddress((void**)&vb, g_v);
    cudaGetSymbolAddress((void**)&ab, g_attn);
    cudaGetSymbolAddress((void**)&bb, g_bias);
    cudaGetSymbolAddress((void**)&inh, g_in_h);
    cudaGetSymbolAddress((void**)&wh, g_w_h);

    const int IN  = M_DIM * E_DIM;
    const int WSZ = E_DIM * E_DIM;

    static int smem_set = 0;
    const int gemm_smem = 3 * 2 * GSTAGEH * (int)sizeof(__half);   // 61440
    const int attn_smem = ATTN_SMEM_HALFS * (int)sizeof(__half);   // 55296
    if (!smem_set) {
        cudaFuncSetAttribute(gemm_kernel<0>, cudaFuncAttributeMaxDynamicSharedMemorySize, gemm_smem);
        cudaFuncSetAttribute(gemm_kernel<1>, cudaFuncAttributeMaxDynamicSharedMemorySize, gemm_smem);
        cudaFuncSetAttribute(attn_kernel, cudaFuncAttributeMaxDynamicSharedMemorySize, attn_smem);
        smem_set = 1;
    }

    tohalf_kernel<<<(3 * IN + 4 * WSZ) / 4 / 256, 256>>>(
        (const float4*)query, (const float4*)key, (const float4*)value,
        (const float4*)wq, (const float4*)wk, (const float4*)wv, (const float4*)wo,
        inh, wh);

    mask_bias_kernel<<<(B_DIM * T_DIM + 255) / 256, 256>>>(mask, bb);

    GemmArgs qkv;
    qkv.A[0] = inh;           qkv.A[1] = inh + IN;      qkv.A[2] = inh + 2 * IN;
    qkv.W[0] = wh;            qkv.W[1] = wh + WSZ;      qkv.W[2] = wh + 2 * WSZ;
    qkv.bias[0] = bq;         qkv.bias[1] = bk;         qkv.bias[2] = bv;
    qkv.out[0] = qb;          qkv.out[1] = kb;          qkv.out[2] = vb;
    qkv.scale[0] = 0.125f * 1.4426950408889634f;        // D^-0.5 * log2(e)
    qkv.scale[1] = 1.0f;      qkv.scale[2] = 1.0f;

    dim3 gqkv(E_DIM / 128, M_DIM / 128, 3);   // (8, 32, 3)
    gemm_kernel<0><<<gqkv, 256, gemm_smem>>>(qkv);

    dim3 gattn(T_DIM / 128, B_DIM * H_DIM);   // (16, 32) = 512 CTAs
    attn_kernel<<<gattn, 128, attn_smem>>>(qb, kb, vb, bb, ab);

    GemmArgs oargs;
    oargs.A[0] = ab;   oargs.W[0] = wh + 3 * WSZ;  oargs.bias[0] = bo;
    oargs.out[0] = out; oargs.scale[0] = 1.0f;
    oargs.A[1] = oargs.A[2] = ab; oargs.W[1] = oargs.W[2] = wh;
    oargs.bias[1] = oargs.bias[2] = bo; oargs.out[1] = oargs.out[2] = (void*)out;
    oargs.scale[1] = oargs.scale[2] = 1.0f;

    dim3 gop(E_DIM / 128, M_DIM / 128, 1);    // (8, 32)
    gemm_kernel<1><<<gop, 256, gemm_smem>>>(oargs);
}